// round 10
// baseline (speedup 1.0000x reference)
#include <cuda_runtime.h>
#include <math_constants.h>

#define K_LEN 1024
#define I_LEN 8192
#define DIM   128
#define FULLM 0xffffffffu

// Scratch (alloc-free rule: __device__ globals)
__device__ float g_C[K_LEN * I_LEN];   // cost matrix -> row-cumsum S (in place)
__device__ float g_k2[K_LEN];
__device__ float g_x2[I_LEN];

// ---------------------------------------------------------------------------
// Kernel 1: squared row norms for both inputs. One warp per row.
// ---------------------------------------------------------------------------
__global__ void norms_kernel(const float* __restrict__ kern,
                             const float* __restrict__ x) {
    int warp = (blockIdx.x * blockDim.x + threadIdx.x) >> 5;
    int lane = threadIdx.x & 31;
    if (warp >= K_LEN + I_LEN) return;
    const float* row = (warp < K_LEN) ? (kern + warp * DIM)
                                      : (x + (warp - K_LEN) * DIM);
    float4 v = ((const float4*)row)[lane];
    float s = v.x * v.x + v.y * v.y + v.z * v.z + v.w * v.w;
#pragma unroll
    for (int off = 16; off; off >>= 1) s += __shfl_xor_sync(FULLM, s, off);
    if (lane == 0) {
        if (warp < K_LEN) g_k2[warp] = s;
        else              g_x2[warp - K_LEN] = s;
    }
}

// ---------------------------------------------------------------------------
// Kernel 2: C[m][n] = max(k2[m] + x2[n] - 2*<kern_m, x_n>, 0)
// 128x128 tile, BK=8, 256 threads, 8x8 microtile, double-buffered smem.
// ---------------------------------------------------------------------------
#define BM 128
#define BN 128
#define BK 8

__global__ __launch_bounds__(256, 2) void cost_gemm(const float* __restrict__ A,
                                                    const float* __restrict__ B) {
    __shared__ float As[2][BK][BM + 4];
    __shared__ float Bs[2][BK][BN + 4];
    const int tid = threadIdx.x;
    const int m0 = blockIdx.y * BM;
    const int n0 = blockIdx.x * BN;
    const int lr = tid >> 1;
    const int lc = (tid & 1) * 4;
    const int tx = tid & 15;
    const int ty = tid >> 4;

    float acc[8][8];
#pragma unroll
    for (int i = 0; i < 8; i++)
#pragma unroll
        for (int j = 0; j < 8; j++) acc[i][j] = 0.0f;

    {
        float4 va = *(const float4*)(A + (size_t)(m0 + lr) * DIM + lc);
        float4 vb = *(const float4*)(B + (size_t)(n0 + lr) * DIM + lc);
        As[0][lc + 0][lr] = va.x; As[0][lc + 1][lr] = va.y;
        As[0][lc + 2][lr] = va.z; As[0][lc + 3][lr] = va.w;
        Bs[0][lc + 0][lr] = vb.x; Bs[0][lc + 1][lr] = vb.y;
        Bs[0][lc + 2][lr] = vb.z; Bs[0][lc + 3][lr] = vb.w;
    }
    __syncthreads();

    int buf = 0;
    for (int k0 = 0; k0 < DIM; k0 += BK) {
        const bool has_next = (k0 + BK < DIM);
        float4 na, nb;
        if (has_next) {
            na = *(const float4*)(A + (size_t)(m0 + lr) * DIM + k0 + BK + lc);
            nb = *(const float4*)(B + (size_t)(n0 + lr) * DIM + k0 + BK + lc);
        }
#pragma unroll
        for (int k = 0; k < BK; k++) {
            float a[8], b[8];
            *(float4*)(a)     = *(const float4*)&As[buf][k][ty * 8];
            *(float4*)(a + 4) = *(const float4*)&As[buf][k][ty * 8 + 4];
            *(float4*)(b)     = *(const float4*)&Bs[buf][k][tx * 8];
            *(float4*)(b + 4) = *(const float4*)&Bs[buf][k][tx * 8 + 4];
#pragma unroll
            for (int i = 0; i < 8; i++)
#pragma unroll
                for (int j = 0; j < 8; j++)
                    acc[i][j] += a[i] * b[j];
        }
        if (has_next) {
            const int nbuf = buf ^ 1;
            As[nbuf][lc + 0][lr] = na.x; As[nbuf][lc + 1][lr] = na.y;
            As[nbuf][lc + 2][lr] = na.z; As[nbuf][lc + 3][lr] = na.w;
            Bs[nbuf][lc + 0][lr] = nb.x; Bs[nbuf][lc + 1][lr] = nb.y;
            Bs[nbuf][lc + 2][lr] = nb.z; Bs[nbuf][lc + 3][lr] = nb.w;
            __syncthreads();
            buf = nbuf;
        }
    }

    float x2v[8];
#pragma unroll
    for (int j = 0; j < 8; j++) x2v[j] = g_x2[n0 + tx * 8 + j];
#pragma unroll
    for (int i = 0; i < 8; i++) {
        const int m = m0 + ty * 8 + i;
        const float k2 = g_k2[m];
        float4 o0, o1;
        o0.x = fmaxf(k2 + x2v[0] - 2.0f * acc[i][0], 0.0f);
        o0.y = fmaxf(k2 + x2v[1] - 2.0f * acc[i][1], 0.0f);
        o0.z = fmaxf(k2 + x2v[2] - 2.0f * acc[i][2], 0.0f);
        o0.w = fmaxf(k2 + x2v[3] - 2.0f * acc[i][3], 0.0f);
        o1.x = fmaxf(k2 + x2v[4] - 2.0f * acc[i][4], 0.0f);
        o1.y = fmaxf(k2 + x2v[5] - 2.0f * acc[i][5], 0.0f);
        o1.z = fmaxf(k2 + x2v[6] - 2.0f * acc[i][6], 0.0f);
        o1.w = fmaxf(k2 + x2v[7] - 2.0f * acc[i][7], 0.0f);
        float* dst = g_C + (size_t)m * I_LEN + n0 + tx * 8;
        *(float4*)(dst)     = o0;
        *(float4*)(dst + 4) = o1;
    }
}

// ---------------------------------------------------------------------------
// Kernel 2.5: in-place row-wise cumsum. One CTA (256 thr) per row.
// ---------------------------------------------------------------------------
__global__ __launch_bounds__(256) void rowcumsum() {
    __shared__ float part[8];
    const int r    = blockIdx.x;
    const int tid  = threadIdx.x;
    const int lane = tid & 31;
    const int wid  = tid >> 5;
    float4* rowp = (float4*)(g_C + (size_t)r * I_LEN + tid * 32);

    float4 V[8];
#pragma unroll
    for (int i = 0; i < 8; i++) V[i] = rowp[i];
    float* v = (float*)V;
#pragma unroll
    for (int j = 1; j < 32; j++) v[j] = v[j] + v[j - 1];

    float W = v[31];
#pragma unroll
    for (int off = 1; off < 32; off <<= 1) {
        float u = __shfl_up_sync(FULLM, W, off);
        if (lane >= off) W += u;
    }
    if (lane == 31) part[wid] = W;
    float ex = __shfl_up_sync(FULLM, W, 1);
    if (lane == 0) ex = 0.0f;
    __syncthreads();
    float woff = 0.0f;
#pragma unroll
    for (int k = 0; k < 7; k++)
        if (k < wid) woff += part[k];
    float off0 = woff + ex;
#pragma unroll
    for (int j = 0; j < 32; j++) v[j] += off0;
#pragma unroll
    for (int i = 0; i < 8; i++) rowp[i] = V[i];
}

// ---------------------------------------------------------------------------
// Kernel 3: DTW DP with precomputed S = rowcumsum(c).
//   D_r[j] = S_r[j] + min_{l<=j} z_r[l]
//   z_r[j] = min(D_{r-1}[j-1], D_{r-1}[j]) - S_r[j-1]   (costs cancel)
// 512 threads x 16 cols. NOTE: macro-local row variable is `rr` — it MUST NOT
// be named `r` (callers pass `r + 1`, which would self-initialize a shadow).
// ---------------------------------------------------------------------------
#define DTPB 512
#define DCPT 16

__global__ __launch_bounds__(DTPB, 1) void dtw_dp(float* __restrict__ out,
                                                  int out_size) {
    __shared__ float sh_lastD[DTPB];
    __shared__ float sh_part[16];
    const float INF = CUDART_INF_F;
    const int tid  = threadIdx.x;
    const int lane = tid & 31;
    const int wid  = tid >> 5;
    const float* base = g_C + (size_t)tid * DCPT;

    for (int i = tid; i < out_size; i += DTPB)
        if (i > 0) out[i] = 0.0f;

    float M[DCPT];
#pragma unroll
    for (int j = 0; j < DCPT; j++) M[j] = INF;
    float d0 = (tid == 0) ? 0.0f : INF;
    sh_lastD[tid] = INF;
    float lastOut = INF;

    float4 A4[4], B4[4];
#pragma unroll
    for (int i = 0; i < 4; i++) A4[i] = ((const float4*)base)[i];
    float sm1_cur = 0.0f;          // lane-0 threads: S[row][tid*16 - 1]
    if (lane == 0 && tid > 0) sm1_cur = g_C[tid * DCPT - 1];
    __syncthreads();

#define ROW(R_, S4, P4)                                                        \
    {                                                                          \
        const int rr = (R_);                                                   \
        const int rn = (rr + 1 < K_LEN) ? rr + 1 : rr;                         \
        /* prefetch next row's S (disjoint float4 regs) */                     \
        {                                                                      \
            const float4* np = (const float4*)(base + (size_t)rn * I_LEN);     \
            _Pragma("unroll")                                                  \
            for (int i = 0; i < 4; i++) P4[i] = np[i];                         \
        }                                                                      \
        float sm1_nxt_ = 0.0f;                                                 \
        if (lane == 0 && tid > 0)                                              \
            sm1_nxt_ = __ldg(g_C + (size_t)rn * I_LEN + tid * DCPT - 1);       \
        const float* Sf = (const float*)S4;                                    \
        float shf_sm1 = __shfl_up_sync(FULLM, Sf[15], 1);                      \
        float sm1 = (lane == 0) ? sm1_cur : shf_sm1;                           \
        float nbr = (tid > 0) ? sh_lastD[tid - 1] : INF;                       \
        M[0] = fminf(nbr, d0);                                                 \
        float pz[DCPT];                                                        \
        pz[0] = M[0] - sm1;                                                    \
        _Pragma("unroll")                                                      \
        for (int j = 1; j < DCPT; j++)                                         \
            pz[j] = fminf(pz[j - 1], M[j] - Sf[j - 1]);                        \
        float W = pz[DCPT - 1];                                                \
        _Pragma("unroll")                                                      \
        for (int off = 1; off < 32; off <<= 1) {                               \
            float u = __shfl_up_sync(FULLM, W, off);                           \
            if (lane >= off) W = fminf(W, u);                                  \
        }                                                                      \
        if (lane == 31) sh_part[wid] = W;                                      \
        float ex = __shfl_up_sync(FULLM, W, 1);                                \
        if (lane == 0) ex = INF;                                               \
        __syncthreads();                                                       \
        float Pp = sh_part[lane & 15];                                         \
        _Pragma("unroll")                                                      \
        for (int off = 1; off < 16; off <<= 1) {                               \
            float u = __shfl_up_sync(FULLM, Pp, off);                          \
            if (lane >= off) Pp = fminf(Pp, u);                                \
        }                                                                      \
        float wmin = (wid == 0) ? INF : __shfl_sync(FULLM, Pp, wid - 1);       \
        float Min = fminf(wmin, ex);                                           \
        float dprev = Sf[0] + fminf(Min, pz[0]);                               \
        d0 = dprev;                                                            \
        _Pragma("unroll")                                                      \
        for (int j = 1; j < DCPT; j++) {                                       \
            float dj = Sf[j] + fminf(Min, pz[j]);                              \
            M[j] = fminf(dprev, dj);                                           \
            dprev = dj;                                                        \
        }                                                                      \
        sh_lastD[tid] = dprev;                                                 \
        lastOut = dprev;                                                       \
        sm1_cur = sm1_nxt_;                                                    \
        __syncthreads();                                                       \
    }

    for (int r = 0; r < K_LEN; r += 2) {
        ROW(r, A4, B4)
        ROW(r + 1, B4, A4)
    }
#undef ROW

    if (tid == DTPB - 1) out[0] = lastOut;
}

// ---------------------------------------------------------------------------
extern "C" void kernel_launch(void* const* d_in, const int* in_sizes, int n_in,
                              void* d_out, int out_size) {
    const float* kern = (const float*)d_in[0];
    const float* x    = (const float*)d_in[1];
    if (n_in >= 2 && in_sizes[0] == I_LEN * DIM && in_sizes[1] == K_LEN * DIM) {
        kern = (const float*)d_in[1];
        x    = (const float*)d_in[0];
    }

    int nwarp_rows = K_LEN + I_LEN;
    norms_kernel<<<(nwarp_rows + 7) / 8, 256>>>(kern, x);

    dim3 grid(I_LEN / BN, K_LEN / BM);
    cost_gemm<<<grid, 256>>>(kern, x);

    rowcumsum<<<K_LEN, 256>>>();

    dtw_dp<<<1, DTPB>>>((float*)d_out, out_size);
}

// round 11
// speedup vs baseline: 1.8908x; 1.8908x over previous
#include <cuda_runtime.h>
#include <math_constants.h>

#define K_LEN 1024
#define I_LEN 8192
#define DIM   128
#define FULLM 0xffffffffu

#define NB   16      // row bands (CTAs)
#define BR   64      // rows per band
#define NCH  16      // column chunks
#define CW   512     // columns per chunk
#define DTH  128     // DP threads per CTA (4 warps, 4 cols/thread)

// Scratch (alloc-free rule: __device__ globals)
__device__ float g_C[K_LEN * I_LEN];       // 32 MB cost matrix
__device__ float g_k2[K_LEN];
__device__ float g_x2[I_LEN];
__device__ float g_row[NB][I_LEN];         // bottom-row D of each band
__device__ unsigned g_flag[NB][NCH];       // chunk-done flags

// ---------------------------------------------------------------------------
// Kernel 1: squared row norms + zero the wavefront flags.
// ---------------------------------------------------------------------------
__global__ void norms_kernel(const float* __restrict__ kern,
                             const float* __restrict__ x) {
    int gtid = blockIdx.x * blockDim.x + threadIdx.x;
    if (gtid < NB * NCH) ((unsigned*)g_flag)[gtid] = 0u;

    int warp = gtid >> 5;
    int lane = threadIdx.x & 31;
    if (warp >= K_LEN + I_LEN) return;
    const float* row = (warp < K_LEN) ? (kern + warp * DIM)
                                      : (x + (warp - K_LEN) * DIM);
    float4 v = ((const float4*)row)[lane];
    float s = v.x * v.x + v.y * v.y + v.z * v.z + v.w * v.w;
#pragma unroll
    for (int off = 16; off; off >>= 1) s += __shfl_xor_sync(FULLM, s, off);
    if (lane == 0) {
        if (warp < K_LEN) g_k2[warp] = s;
        else              g_x2[warp - K_LEN] = s;
    }
}

// ---------------------------------------------------------------------------
// Kernel 2: C[m][n] = max(k2[m] + x2[n] - 2*<kern_m, x_n>, 0)   (R7 version)
// ---------------------------------------------------------------------------
#define BM 128
#define BN 128
#define BK 8

__global__ __launch_bounds__(256, 2) void cost_gemm(const float* __restrict__ A,
                                                    const float* __restrict__ B) {
    __shared__ float As[2][BK][BM + 4];
    __shared__ float Bs[2][BK][BN + 4];
    const int tid = threadIdx.x;
    const int m0 = blockIdx.y * BM;
    const int n0 = blockIdx.x * BN;
    const int lr = tid >> 1;
    const int lc = (tid & 1) * 4;
    const int tx = tid & 15;
    const int ty = tid >> 4;

    float acc[8][8];
#pragma unroll
    for (int i = 0; i < 8; i++)
#pragma unroll
        for (int j = 0; j < 8; j++) acc[i][j] = 0.0f;

    {
        float4 va = *(const float4*)(A + (size_t)(m0 + lr) * DIM + lc);
        float4 vb = *(const float4*)(B + (size_t)(n0 + lr) * DIM + lc);
        As[0][lc + 0][lr] = va.x; As[0][lc + 1][lr] = va.y;
        As[0][lc + 2][lr] = va.z; As[0][lc + 3][lr] = va.w;
        Bs[0][lc + 0][lr] = vb.x; Bs[0][lc + 1][lr] = vb.y;
        Bs[0][lc + 2][lr] = vb.z; Bs[0][lc + 3][lr] = vb.w;
    }
    __syncthreads();

    int buf = 0;
    for (int k0 = 0; k0 < DIM; k0 += BK) {
        const bool has_next = (k0 + BK < DIM);
        float4 na, nb;
        if (has_next) {
            na = *(const float4*)(A + (size_t)(m0 + lr) * DIM + k0 + BK + lc);
            nb = *(const float4*)(B + (size_t)(n0 + lr) * DIM + k0 + BK + lc);
        }
#pragma unroll
        for (int k = 0; k < BK; k++) {
            float a[8], b[8];
            *(float4*)(a)     = *(const float4*)&As[buf][k][ty * 8];
            *(float4*)(a + 4) = *(const float4*)&As[buf][k][ty * 8 + 4];
            *(float4*)(b)     = *(const float4*)&Bs[buf][k][tx * 8];
            *(float4*)(b + 4) = *(const float4*)&Bs[buf][k][tx * 8 + 4];
#pragma unroll
            for (int i = 0; i < 8; i++)
#pragma unroll
                for (int j = 0; j < 8; j++)
                    acc[i][j] += a[i] * b[j];
        }
        if (has_next) {
            const int nbuf = buf ^ 1;
            As[nbuf][lc + 0][lr] = na.x; As[nbuf][lc + 1][lr] = na.y;
            As[nbuf][lc + 2][lr] = na.z; As[nbuf][lc + 3][lr] = na.w;
            Bs[nbuf][lc + 0][lr] = nb.x; Bs[nbuf][lc + 1][lr] = nb.y;
            Bs[nbuf][lc + 2][lr] = nb.z; Bs[nbuf][lc + 3][lr] = nb.w;
            __syncthreads();
            buf = nbuf;
        }
    }

    float x2v[8];
#pragma unroll
    for (int j = 0; j < 8; j++) x2v[j] = g_x2[n0 + tx * 8 + j];
#pragma unroll
    for (int i = 0; i < 8; i++) {
        const int m = m0 + ty * 8 + i;
        const float k2 = g_k2[m];
        float4 o0, o1;
        o0.x = fmaxf(k2 + x2v[0] - 2.0f * acc[i][0], 0.0f);
        o0.y = fmaxf(k2 + x2v[1] - 2.0f * acc[i][1], 0.0f);
        o0.z = fmaxf(k2 + x2v[2] - 2.0f * acc[i][2], 0.0f);
        o0.w = fmaxf(k2 + x2v[3] - 2.0f * acc[i][3], 0.0f);
        o1.x = fmaxf(k2 + x2v[4] - 2.0f * acc[i][4], 0.0f);
        o1.y = fmaxf(k2 + x2v[5] - 2.0f * acc[i][5], 0.0f);
        o1.z = fmaxf(k2 + x2v[6] - 2.0f * acc[i][6], 0.0f);
        o1.w = fmaxf(k2 + x2v[7] - 2.0f * acc[i][7], 0.0f);
        float* dst = g_C + (size_t)m * I_LEN + n0 + tx * 8;
        *(float4*)(dst)     = o0;
        *(float4*)(dst + 4) = o1;
    }
}

// ---------------------------------------------------------------------------
// Kernel 3: block-wavefront DTW DP.
// CTA b owns rows [64b, 64b+64). Chunks of 512 cols processed left->right.
// CTA b waits on g_flag[b-1][j] (one acquire-poll per chunk, ~22K cyc slack),
// reads the top boundary from g_row[b-1], keeps left boundaries in smem
// ping-pong, and runs the R1 (C,E) pair-scan per row over 4 warps.
// ---------------------------------------------------------------------------
__global__ __launch_bounds__(DTH, 1) void dtw_wave(float* __restrict__ out,
                                                   int out_size) {
    __shared__ float sh_bound[DTH];
    __shared__ float shC[4], shE[4];
    __shared__ float Dl[2][BR];      // left-boundary D per row, ping-pong
    const float INF = CUDART_INF_F;
    const int b    = blockIdx.x;
    const int tid  = threadIdx.x;
    const int lane = tid & 31;
    const int wid  = tid >> 5;

    if (b == 0)
        for (int i = tid; i < out_size; i += DTH)
            if (i > 0) out[i] = 0.0f;
    if (tid < BR) Dl[0][tid] = INF;   // chunk 0 has no left neighbor

    float res = INF;

    for (int j = 0; j < NCH; j++) {
        const int sel = j & 1;
        if (b > 0 && tid == 0) {
            unsigned v;
            do {
                asm volatile("ld.acquire.gpu.global.u32 %0, [%1];"
                             : "=r"(v) : "l"(&g_flag[b - 1][j]));
            } while (!v);
        }
        __syncthreads();

        // top boundary (row above the band) for r = 0
        float Dp0, Dp1, Dp2, Dp3;
        if (b > 0) {
            float4 tv = *(const float4*)(&g_row[b - 1][j * CW + 4 * tid]);
            Dp0 = tv.x; Dp1 = tv.y; Dp2 = tv.z; Dp3 = tv.w;
        } else {
            Dp0 = Dp1 = Dp2 = Dp3 = INF;
        }
        // top-left diagonal value for thread 0, row 0
        float dlc;
        if (b > 0) dlc = (j > 0) ? g_row[b - 1][j * CW - 1] : INF;
        else       dlc = (j == 0) ? 0.0f : INF;   // D[-1][-1] = 0
        sh_bound[tid] = Dp3;
        __syncthreads();

        const float* cbase = g_C + (size_t)(b * BR) * I_LEN + j * CW + 4 * tid;
        float4 cc = *(const float4*)cbase;

        for (int r = 0; r < BR; r++) {
            float4 pf;
            if (r + 1 < BR)
                pf = *(const float4*)(cbase + (size_t)(r + 1) * I_LEN);

            float dleft = (tid == 0) ? dlc : sh_bound[tid - 1];
            const float c0 = cc.x, c1 = cc.y, c2 = cc.z, c3 = cc.w;
            float e0 = fminf(dleft, Dp0) + c0;
            float e1 = fminf(Dp0, Dp1) + c1;
            float e2 = fminf(Dp1, Dp2) + c2;
            float e3 = fminf(Dp2, Dp3) + c3;

            float Cl = c0 + c1 + c2 + c3;
            float El = e0;
            El = fminf(El + c1, e1);
            El = fminf(El + c2, e2);
            El = fminf(El + c3, e3);

#pragma unroll
            for (int off = 1; off < 32; off <<= 1) {
                float Cu = __shfl_up_sync(FULLM, Cl, off);
                float Eu = __shfl_up_sync(FULLM, El, off);
                if (lane >= off) {
                    El = fminf(Eu + Cl, El);
                    Cl = Cu + Cl;
                }
            }
            if (lane == 31) { shC[wid] = Cl; shE[wid] = El; }
            __syncthreads();

            float wC = 0.0f, wE = INF;
#pragma unroll
            for (int k = 0; k < 3; k++) {
                if (k < wid) {
                    wE = fminf(wE + shC[k], shE[k]);
                    wC = wC + shC[k];
                }
            }
            float exC = __shfl_up_sync(FULLM, Cl, 1);
            float exE = __shfl_up_sync(FULLM, El, 1);
            if (lane == 0) { exC = 0.0f; exE = INF; }
            float Cex = wC + exC;
            float Eex = fminf(wE + exC, exE);

            float Dlv = Dl[sel][r];                 // D[R][chunk_left - 1]
            float Din = fminf(Eex, Dlv + Cex);

            float D0 = fminf(Din + c0, e0);
            float D1 = fminf(D0 + c1, e1);
            float D2 = fminf(D1 + c2, e2);
            float D3 = fminf(D2 + c3, e3);

            dlc = Dlv;                               // diag for next row (tid 0)
            if (tid == DTH - 1) Dl[sel ^ 1][r] = D3; // left boundary, next chunk
            if (r == BR - 1) {
                if (b < NB - 1)
                    *(float4*)(&g_row[b][j * CW + 4 * tid]) =
                        make_float4(D0, D1, D2, D3);
                res = D3;
            }
            sh_bound[tid] = D3;
            Dp0 = D0; Dp1 = D1; Dp2 = D2; Dp3 = D3;
            cc = pf;
            __syncthreads();
        }

        if (b < NB - 1) {
            __threadfence();
            if (tid == 0)
                asm volatile("st.release.gpu.global.u32 [%0], %1;"
                             :: "l"(&g_flag[b][j]), "r"(1u));
        }
    }

    if (b == NB - 1 && tid == DTH - 1) out[0] = res;
}

// ---------------------------------------------------------------------------
extern "C" void kernel_launch(void* const* d_in, const int* in_sizes, int n_in,
                              void* d_out, int out_size) {
    const float* kern = (const float*)d_in[0];
    const float* x    = (const float*)d_in[1];
    if (n_in >= 2 && in_sizes[0] == I_LEN * DIM && in_sizes[1] == K_LEN * DIM) {
        kern = (const float*)d_in[1];
        x    = (const float*)d_in[0];
    }

    int nwarp_rows = K_LEN + I_LEN;
    norms_kernel<<<(nwarp_rows + 7) / 8, 256>>>(kern, x);

    dim3 grid(I_LEN / BN, K_LEN / BM);
    cost_gemm<<<grid, 256>>>(kern, x);

    dtw_wave<<<NB, DTH>>>((float*)d_out, out_size);
}

// round 12
// speedup vs baseline: 2.4102x; 1.2747x over previous
#include <cuda_runtime.h>
#include <math_constants.h>

#define K_LEN 1024
#define I_LEN 8192
#define DIM   128
#define FULLM 0xffffffffu

#define NB   64      // row bands (CTAs)
#define BR   16      // rows per band
#define NCH  16      // column chunks
#define CW   512     // columns per chunk
#define DTH  128     // DP threads per CTA (4 warps, 4 cols/thread)

// Scratch (alloc-free rule: __device__ globals)
__device__ float g_C[K_LEN * I_LEN];       // 32 MB cost matrix
__device__ float g_k2[K_LEN];
__device__ float g_x2[I_LEN];
__device__ float g_row[NB][I_LEN];         // bottom-row D of each band
__device__ unsigned g_flag[NB][NCH];       // chunk-done flags

// ---------------------------------------------------------------------------
// Kernel 1: squared row norms + zero the wavefront flags.
// ---------------------------------------------------------------------------
__global__ void norms_kernel(const float* __restrict__ kern,
                             const float* __restrict__ x) {
    int gtid = blockIdx.x * blockDim.x + threadIdx.x;
    if (gtid < NB * NCH) ((unsigned*)g_flag)[gtid] = 0u;

    int warp = gtid >> 5;
    int lane = threadIdx.x & 31;
    if (warp >= K_LEN + I_LEN) return;
    const float* row = (warp < K_LEN) ? (kern + warp * DIM)
                                      : (x + (warp - K_LEN) * DIM);
    float4 v = ((const float4*)row)[lane];
    float s = v.x * v.x + v.y * v.y + v.z * v.z + v.w * v.w;
#pragma unroll
    for (int off = 16; off; off >>= 1) s += __shfl_xor_sync(FULLM, s, off);
    if (lane == 0) {
        if (warp < K_LEN) g_k2[warp] = s;
        else              g_x2[warp - K_LEN] = s;
    }
}

// ---------------------------------------------------------------------------
// Kernel 2: C[m][n] = max(k2[m] + x2[n] - 2*<kern_m, x_n>, 0)   (R7 version)
// ---------------------------------------------------------------------------
#define BM 128
#define BN 128
#define BK 8

__global__ __launch_bounds__(256, 2) void cost_gemm(const float* __restrict__ A,
                                                    const float* __restrict__ B) {
    __shared__ float As[2][BK][BM + 4];
    __shared__ float Bs[2][BK][BN + 4];
    const int tid = threadIdx.x;
    const int m0 = blockIdx.y * BM;
    const int n0 = blockIdx.x * BN;
    const int lr = tid >> 1;
    const int lc = (tid & 1) * 4;
    const int tx = tid & 15;
    const int ty = tid >> 4;

    float acc[8][8];
#pragma unroll
    for (int i = 0; i < 8; i++)
#pragma unroll
        for (int j = 0; j < 8; j++) acc[i][j] = 0.0f;

    {
        float4 va = *(const float4*)(A + (size_t)(m0 + lr) * DIM + lc);
        float4 vb = *(const float4*)(B + (size_t)(n0 + lr) * DIM + lc);
        As[0][lc + 0][lr] = va.x; As[0][lc + 1][lr] = va.y;
        As[0][lc + 2][lr] = va.z; As[0][lc + 3][lr] = va.w;
        Bs[0][lc + 0][lr] = vb.x; Bs[0][lc + 1][lr] = vb.y;
        Bs[0][lc + 2][lr] = vb.z; Bs[0][lc + 3][lr] = vb.w;
    }
    __syncthreads();

    int buf = 0;
    for (int k0 = 0; k0 < DIM; k0 += BK) {
        const bool has_next = (k0 + BK < DIM);
        float4 na, nb;
        if (has_next) {
            na = *(const float4*)(A + (size_t)(m0 + lr) * DIM + k0 + BK + lc);
            nb = *(const float4*)(B + (size_t)(n0 + lr) * DIM + k0 + BK + lc);
        }
#pragma unroll
        for (int k = 0; k < BK; k++) {
            float a[8], b[8];
            *(float4*)(a)     = *(const float4*)&As[buf][k][ty * 8];
            *(float4*)(a + 4) = *(const float4*)&As[buf][k][ty * 8 + 4];
            *(float4*)(b)     = *(const float4*)&Bs[buf][k][tx * 8];
            *(float4*)(b + 4) = *(const float4*)&Bs[buf][k][tx * 8 + 4];
#pragma unroll
            for (int i = 0; i < 8; i++)
#pragma unroll
                for (int j = 0; j < 8; j++)
                    acc[i][j] += a[i] * b[j];
        }
        if (has_next) {
            const int nbuf = buf ^ 1;
            As[nbuf][lc + 0][lr] = na.x; As[nbuf][lc + 1][lr] = na.y;
            As[nbuf][lc + 2][lr] = na.z; As[nbuf][lc + 3][lr] = na.w;
            Bs[nbuf][lc + 0][lr] = nb.x; Bs[nbuf][lc + 1][lr] = nb.y;
            Bs[nbuf][lc + 2][lr] = nb.z; Bs[nbuf][lc + 3][lr] = nb.w;
            __syncthreads();
            buf = nbuf;
        }
    }

    float x2v[8];
#pragma unroll
    for (int j = 0; j < 8; j++) x2v[j] = g_x2[n0 + tx * 8 + j];
#pragma unroll
    for (int i = 0; i < 8; i++) {
        const int m = m0 + ty * 8 + i;
        const float k2 = g_k2[m];
        float4 o0, o1;
        o0.x = fmaxf(k2 + x2v[0] - 2.0f * acc[i][0], 0.0f);
        o0.y = fmaxf(k2 + x2v[1] - 2.0f * acc[i][1], 0.0f);
        o0.z = fmaxf(k2 + x2v[2] - 2.0f * acc[i][2], 0.0f);
        o0.w = fmaxf(k2 + x2v[3] - 2.0f * acc[i][3], 0.0f);
        o1.x = fmaxf(k2 + x2v[4] - 2.0f * acc[i][4], 0.0f);
        o1.y = fmaxf(k2 + x2v[5] - 2.0f * acc[i][5], 0.0f);
        o1.z = fmaxf(k2 + x2v[6] - 2.0f * acc[i][6], 0.0f);
        o1.w = fmaxf(k2 + x2v[7] - 2.0f * acc[i][7], 0.0f);
        float* dst = g_C + (size_t)m * I_LEN + n0 + tx * 8;
        *(float4*)(dst)     = o0;
        *(float4*)(dst + 4) = o1;
    }
}

// ---------------------------------------------------------------------------
// Kernel 3: block-wavefront DTW DP.  (R11 inner loop, re-tiled 64x16 bands)
// CTA b owns rows [BR*b, BR*b+BR). Chunks of 512 cols processed left->right.
// Critical path: (NCH + NB - 1) * BR = 1264 row-steps (was 1984).
// ---------------------------------------------------------------------------
__global__ __launch_bounds__(DTH, 1) void dtw_wave(float* __restrict__ out,
                                                   int out_size) {
    __shared__ float sh_bound[DTH];
    __shared__ float shC[4], shE[4];
    __shared__ float Dl[2][BR];      // left-boundary D per row, ping-pong
    const float INF = CUDART_INF_F;
    const int b    = blockIdx.x;
    const int tid  = threadIdx.x;
    const int lane = tid & 31;
    const int wid  = tid >> 5;

    if (b == 0)
        for (int i = tid; i < out_size; i += DTH)
            if (i > 0) out[i] = 0.0f;
    if (tid < BR) Dl[0][tid] = INF;   // chunk 0 has no left neighbor

    float res = INF;

    for (int j = 0; j < NCH; j++) {
        const int sel = j & 1;
        if (b > 0 && tid == 0) {
            unsigned v;
            do {
                asm volatile("ld.acquire.gpu.global.u32 %0, [%1];"
                             : "=r"(v) : "l"(&g_flag[b - 1][j]));
            } while (!v);
        }
        __syncthreads();

        // top boundary (row above the band) for r = 0
        float Dp0, Dp1, Dp2, Dp3;
        if (b > 0) {
            float4 tv = *(const float4*)(&g_row[b - 1][j * CW + 4 * tid]);
            Dp0 = tv.x; Dp1 = tv.y; Dp2 = tv.z; Dp3 = tv.w;
        } else {
            Dp0 = Dp1 = Dp2 = Dp3 = INF;
        }
        // top-left diagonal value for thread 0, row 0
        float dlc;
        if (b > 0) dlc = (j > 0) ? g_row[b - 1][j * CW - 1] : INF;
        else       dlc = (j == 0) ? 0.0f : INF;   // D[-1][-1] = 0
        sh_bound[tid] = Dp3;
        __syncthreads();

        const float* cbase = g_C + (size_t)(b * BR) * I_LEN + j * CW + 4 * tid;
        float4 cc = *(const float4*)cbase;

        for (int r = 0; r < BR; r++) {
            float4 pf;
            if (r + 1 < BR)
                pf = *(const float4*)(cbase + (size_t)(r + 1) * I_LEN);

            float dleft = (tid == 0) ? dlc : sh_bound[tid - 1];
            const float c0 = cc.x, c1 = cc.y, c2 = cc.z, c3 = cc.w;
            float e0 = fminf(dleft, Dp0) + c0;
            float e1 = fminf(Dp0, Dp1) + c1;
            float e2 = fminf(Dp1, Dp2) + c2;
            float e3 = fminf(Dp2, Dp3) + c3;

            float Cl = c0 + c1 + c2 + c3;
            float El = e0;
            El = fminf(El + c1, e1);
            El = fminf(El + c2, e2);
            El = fminf(El + c3, e3);

#pragma unroll
            for (int off = 1; off < 32; off <<= 1) {
                float Cu = __shfl_up_sync(FULLM, Cl, off);
                float Eu = __shfl_up_sync(FULLM, El, off);
                if (lane >= off) {
                    El = fminf(Eu + Cl, El);
                    Cl = Cu + Cl;
                }
            }
            if (lane == 31) { shC[wid] = Cl; shE[wid] = El; }
            __syncthreads();

            float wC = 0.0f, wE = INF;
#pragma unroll
            for (int k = 0; k < 3; k++) {
                if (k < wid) {
                    wE = fminf(wE + shC[k], shE[k]);
                    wC = wC + shC[k];
                }
            }
            float exC = __shfl_up_sync(FULLM, Cl, 1);
            float exE = __shfl_up_sync(FULLM, El, 1);
            if (lane == 0) { exC = 0.0f; exE = INF; }
            float Cex = wC + exC;
            float Eex = fminf(wE + exC, exE);

            float Dlv = Dl[sel][r];                 // D[R][chunk_left - 1]
            float Din = fminf(Eex, Dlv + Cex);

            float D0 = fminf(Din + c0, e0);
            float D1 = fminf(D0 + c1, e1);
            float D2 = fminf(D1 + c2, e2);
            float D3 = fminf(D2 + c3, e3);

            dlc = Dlv;                               // diag for next row (tid 0)
            if (tid == DTH - 1) Dl[sel ^ 1][r] = D3; // left boundary, next chunk
            if (r == BR - 1) {
                if (b < NB - 1)
                    *(float4*)(&g_row[b][j * CW + 4 * tid]) =
                        make_float4(D0, D1, D2, D3);
                res = D3;
            }
            sh_bound[tid] = D3;
            Dp0 = D0; Dp1 = D1; Dp2 = D2; Dp3 = D3;
            cc = pf;
            __syncthreads();
        }

        if (b < NB - 1) {
            __threadfence();
            if (tid == 0)
                asm volatile("st.release.gpu.global.u32 [%0], %1;"
                             :: "l"(&g_flag[b][j]), "r"(1u));
        }
    }

    if (b == NB - 1 && tid == DTH - 1) out[0] = res;
}

// ---------------------------------------------------------------------------
extern "C" void kernel_launch(void* const* d_in, const int* in_sizes, int n_in,
                              void* d_out, int out_size) {
    const float* kern = (const float*)d_in[0];
    const float* x    = (const float*)d_in[1];
    if (n_in >= 2 && in_sizes[0] == I_LEN * DIM && in_sizes[1] == K_LEN * DIM) {
        kern = (const float*)d_in[1];
        x    = (const float*)d_in[0];
    }

    int nwarp_rows = K_LEN + I_LEN;
    norms_kernel<<<(nwarp_rows + 7) / 8, 256>>>(kern, x);

    dim3 grid(I_LEN / BN, K_LEN / BM);
    cost_gemm<<<grid, 256>>>(kern, x);

    dtw_wave<<<NB, DTH>>>((float*)d_out, out_size);
}